// round 2
// baseline (speedup 1.0000x reference)
#include <cuda_runtime.h>
#include <cuda_bf16.h>

#define B_     16
#define S_     4096
#define D_     512
#define PE_DIM 256

__device__ int g_lengths[B_];

// One block per batch row: count mask[b,s]==0 over S.
__global__ void lengths_kernel(const int* __restrict__ mask) {
    int b = blockIdx.x;
    const int4* m = reinterpret_cast<const int4*>(mask + (size_t)b * S_);
    int cnt = 0;
    for (int i = threadIdx.x; i < S_ / 4; i += blockDim.x) {
        int4 v = m[i];
        cnt += (v.x == 0) + (v.y == 0) + (v.z == 0) + (v.w == 0);
    }
    // warp reduce
    #pragma unroll
    for (int off = 16; off > 0; off >>= 1)
        cnt += __shfl_down_sync(0xFFFFFFFFu, cnt, off);
    __shared__ int smem[32];
    int lane = threadIdx.x & 31;
    int wid  = threadIdx.x >> 5;
    if (lane == 0) smem[wid] = cnt;
    __syncthreads();
    if (wid == 0) {
        int nw = blockDim.x >> 5;
        int v = (lane < nw) ? smem[lane] : 0;
        #pragma unroll
        for (int off = 16; off > 0; off >>= 1)
            v += __shfl_down_sync(0xFFFFFFFFu, v, off);
        if (lane == 0) g_lengths[b] = v;
    }
}

// One float4 per thread. D=512 -> 128 float4 per (b,s) row.
__global__ void pe_add_kernel(const float* __restrict__ x,
                              const float* __restrict__ pe,
                              float* __restrict__ out) {
    const int Q = D_ / 4;  // 128 float4 per row
    size_t t = (size_t)blockIdx.x * blockDim.x + threadIdx.x;
    // t in [0, B*S*Q)
    int q = (int)(t & (Q - 1));          // float4 index within row
    size_t row = t >> 7;                 // b*S + s
    int s = (int)(row & (S_ - 1));
    int b = (int)(row >> 12);            // S = 4096 = 2^12

    int d  = q * 4;
    int d2 = d & (PE_DIM - 1);           // d % 256

    float4 xv = reinterpret_cast<const float4*>(x)[t];
    float4 bv = *reinterpret_cast<const float4*>(pe + (size_t)s * PE_DIM + d2);

    float4 o;
    o.x = xv.x + bv.x;
    o.y = xv.y + bv.y;
    o.z = xv.z + bv.z;
    o.w = xv.w + bv.w;

    int len = g_lengths[b];
    if (s < len) {
        int idx = len - 1 - s;           // >= 0 when s < len
        // reversed feature order: pe[idx, 255-d2], 254-d2, 253-d2, 252-d2
        float4 rv = *reinterpret_cast<const float4*>(pe + (size_t)idx * PE_DIM + (252 - d2));
        o.x += rv.w;
        o.y += rv.z;
        o.z += rv.y;
        o.w += rv.x;
    }

    reinterpret_cast<float4*>(out)[t] = o;
}

extern "C" void kernel_launch(void* const* d_in, const int* in_sizes, int n_in,
                              void* d_out, int out_size) {
    const float* x    = (const float*)d_in[0];
    const int*   mask = (const int*)d_in[1];
    const float* pe   = (const float*)d_in[2];
    float* out = (float*)d_out;

    lengths_kernel<<<B_, 256>>>(mask);

    const size_t total4 = (size_t)B_ * S_ * (D_ / 4);  // 8,388,608 float4
    const int threads = 256;
    const int blocks = (int)(total4 / threads);        // 32768
    pe_add_kernel<<<blocks, threads>>>(x, pe, out);
}

// round 3
// speedup vs baseline: 1.0602x; 1.0602x over previous
#include <cuda_runtime.h>
#include <cuda_bf16.h>

#define B_     16
#define S_     4096
#define D_     512
#define PE_DIM 256

__device__ int g_lengths[B_];

// One block per batch row: count mask[b,s]==0 over S.
__global__ void lengths_kernel(const int* __restrict__ mask) {
    int b = blockIdx.x;
    const int4* m = reinterpret_cast<const int4*>(mask + (size_t)b * S_);
    int cnt = 0;
    for (int i = threadIdx.x; i < S_ / 4; i += blockDim.x) {
        int4 v = m[i];
        cnt += (v.x == 0) + (v.y == 0) + (v.z == 0) + (v.w == 0);
    }
    #pragma unroll
    for (int off = 16; off > 0; off >>= 1)
        cnt += __shfl_down_sync(0xFFFFFFFFu, cnt, off);
    __shared__ int smem[32];
    int lane = threadIdx.x & 31;
    int wid  = threadIdx.x >> 5;
    if (lane == 0) smem[wid] = cnt;
    __syncthreads();
    if (wid == 0) {
        int nw = blockDim.x >> 5;
        int v = (lane < nw) ? smem[lane] : 0;
        #pragma unroll
        for (int off = 16; off > 0; off >>= 1)
            v += __shfl_down_sync(0xFFFFFFFFu, v, off);
        if (lane == 0) g_lengths[b] = v;
    }
}

// 4 float4 per thread, front-batched loads. Block covers 1024 consecutive
// float4 (= 8 rows, always within one batch since 1024 | 524288).
__global__ void __launch_bounds__(256) pe_add_kernel(const float4* __restrict__ x,
                                                     const float* __restrict__ pe,
                                                     float4* __restrict__ out) {
    const size_t base = (size_t)blockIdx.x * 1024 + threadIdx.x;

    // ---- phase 1: everything independent of g_lengths (overlaps producer) ----
    float4 xv[4], bv[4];
    int s[4], d2[4];
    #pragma unroll
    for (int i = 0; i < 4; i++) {
        size_t t = base + (size_t)i * 256;
        xv[i] = __ldcs(&x[t]);                   // streaming: don't pollute L2
        int q = (int)(t & 127);                  // float4 index within D row
        size_t row = t >> 7;                     // b*S + s
        s[i]  = (int)(row & (S_ - 1));
        d2[i] = (q * 4) & (PE_DIM - 1);
        bv[i] = *reinterpret_cast<const float4*>(pe + (size_t)s[i] * PE_DIM + d2[i]);
    }
    const int b = (int)(base >> 19);             // batch: 4096*128 float4 per batch

    // ---- wait for lengths_kernel (PDL), then finish ----
    cudaGridDependencySynchronize();
    const int len = g_lengths[b];

    #pragma unroll
    for (int i = 0; i < 4; i++) {
        float4 o;
        o.x = xv[i].x + bv[i].x;
        o.y = xv[i].y + bv[i].y;
        o.z = xv[i].z + bv[i].z;
        o.w = xv[i].w + bv[i].w;
        if (s[i] < len) {
            int idx = len - 1 - s[i];
            float4 rv = *reinterpret_cast<const float4*>(
                pe + (size_t)idx * PE_DIM + (252 - d2[i]));
            o.x += rv.w;
            o.y += rv.z;
            o.z += rv.y;
            o.w += rv.x;
        }
        __stcs(&out[base + (size_t)i * 256], o);  // streaming store
    }
}

extern "C" void kernel_launch(void* const* d_in, const int* in_sizes, int n_in,
                              void* d_out, int out_size) {
    const float* x    = (const float*)d_in[0];
    const int*   mask = (const int*)d_in[1];
    const float* pe   = (const float*)d_in[2];
    float* out = (float*)d_out;

    lengths_kernel<<<B_, 256>>>(mask);

    const size_t total4 = (size_t)B_ * S_ * (D_ / 4);   // 8,388,608 float4
    const unsigned blocks = (unsigned)(total4 / 1024);  // 8192

    cudaLaunchConfig_t cfg = {};
    cfg.gridDim  = dim3(blocks, 1, 1);
    cfg.blockDim = dim3(256, 1, 1);
    cfg.dynamicSmemBytes = 0;
    cfg.stream = 0;
    cudaLaunchAttribute attrs[1];
    attrs[0].id = cudaLaunchAttributeProgrammaticStreamSerialization;
    attrs[0].val.programmaticStreamSerializationAllowed = 1;
    cfg.attrs = attrs;
    cfg.numAttrs = 1;

    cudaLaunchKernelEx(&cfg, pe_add_kernel,
                       (const float4*)x, pe, (float4*)out);
}